// round 12
// baseline (speedup 1.0000x reference)
#include <cuda_runtime.h>
#include <cuda_bf16.h>

// ZBL screened nuclear repulsion:
//   expv = Dij/d * (Zi^p + Zj^p)
//   vij  = sum_k c[k] * exp(-a[k]*expv)
//   out  = segment_sum(vij, idx_i)   (idx_i sorted)
//
// R12: exact R10 skeleton (best basin: ITERS=4, slim idx prefetch, MUFU
// z^p, warp-segmented reduction) with __launch_bounds__(256, 7): forces
// ptxas from 40 -> ~36 regs so a 7th CTA fits per SM (75% -> 87.5%
// theoretical occupancy). The kernel is latency-limited (issue 52%), so
// resident-warp count is the remaining unexercised knob.

#define EPT   4
#define TPB   256
#define ITERS 4

__device__ __forceinline__ float ex2(float x) {
    float y;
    asm("ex2.approx.f32 %0, %1;" : "=f"(y) : "f"(x));
    return y;
}
__device__ __forceinline__ float lg2(float x) {
    float y;
    asm("lg2.approx.f32 %0, %1;" : "=f"(y) : "f"(x));
    return y;
}

// ---------------------------------------------------------------------------
__global__ __launch_bounds__(TPB, 7)
void zbl_main_kernel(const float4* __restrict__ Dij4,
                     const int4*   __restrict__ idx_i4,
                     const int4*   __restrict__ idx_j4,
                     const int*    __restrict__ Z,
                     const float*  __restrict__ p_ptr,
                     const float*  __restrict__ d_ptr,
                     const float*  __restrict__ c_ptr,
                     const float*  __restrict__ a_ptr,
                     float*        __restrict__ out,
                     int V)   // number of 4-edge vectors
{
    const float p    = __ldg(p_ptr);
    const float invd = 1.0f / __ldg(d_ptr);
    const float c0 = __ldg(c_ptr + 0), c1 = __ldg(c_ptr + 1);
    const float c2 = __ldg(c_ptr + 2), c3 = __ldg(c_ptr + 3);
    // b_k = -a_k * log2(e) / d : folds exp->ex2 base change and 1/d
    const float NL2E = -1.4426950408889634f * invd;
    const float b0 = __ldg(a_ptr + 0) * NL2E, b1 = __ldg(a_ptr + 1) * NL2E;
    const float b2 = __ldg(a_ptr + 2) * NL2E, b3 = __ldg(a_ptr + 3) * NL2E;

    const int stride = gridDim.x * blockDim.x;
    int v = blockIdx.x * blockDim.x + threadIdx.x;

    const unsigned m = 0xFFFFFFFFu;
    const int lane = threadIdx.x & 31;

    // ---- prologue: prefetch iteration 0's index vectors (gather roots).
    bool valid = (v < V);
    int4 ii = make_int4(0, 0, 0, 0);
    int4 jj = make_int4(0, 0, 0, 0);
    if (valid) {
        ii = __ldcs(idx_i4 + v);
        jj = __ldcs(idx_j4 + v);
    }

    #pragma unroll 1
    for (int k = 0; k < ITERS; k++) {
        int   cur = -1;     // pending segment id (tail)
        float acc = 0.0f;   // pending segment sum

        // next iteration's index prefetch (issued before this iteration's
        // dependent work so the DRAM hop overlaps the gather+math+scan)
        const int  vn     = v + stride;
        const bool nvalid = (k + 1 < ITERS) && (vn < V);
        int4 ii_n = make_int4(0, 0, 0, 0);
        int4 jj_n = make_int4(0, 0, 0, 0);
        if (nvalid) {
            ii_n = __ldcs(idx_i4 + vn);
            jj_n = __ldcs(idx_j4 + vn);
        }

        if (valid) {
            // ---- Dij load: independent of the gather chain, self-hiding ----
            const float4 dd = __ldcs(Dij4 + v);

            // ---- 8 independent scalar gathers from the input Z array ----
            const int zi0 = __ldg(Z + ii.x), zi1 = __ldg(Z + ii.y);
            const int zi2 = __ldg(Z + ii.z), zi3 = __ldg(Z + ii.w);
            const int zj0 = __ldg(Z + jj.x), zj1 = __ldg(Z + jj.y);
            const int zj2 = __ldg(Z + jj.z), zj3 = __ldg(Z + jj.w);

            // ---- z^p via MUFU: ex2(p*lg2 z); z=0 -> -inf -> 0 = pow(0,p) ----
            const float fi0 = ex2(p * lg2((float)zi0));
            const float fi1 = ex2(p * lg2((float)zi1));
            const float fi2 = ex2(p * lg2((float)zi2));
            const float fi3 = ex2(p * lg2((float)zi3));
            const float fj0 = ex2(p * lg2((float)zj0));
            const float fj1 = ex2(p * lg2((float)zj1));
            const float fj2 = ex2(p * lg2((float)zj2));
            const float fj3 = ex2(p * lg2((float)zj3));

            const float e0 = dd.x * (fi0 + fj0);
            const float e1 = dd.y * (fi1 + fj1);
            const float e2 = dd.z * (fi2 + fj2);
            const float e3 = dd.w * (fi3 + fj3);

            const float v0 = c0*ex2(b0*e0) + c1*ex2(b1*e0) + c2*ex2(b2*e0) + c3*ex2(b3*e0);
            const float v1 = c0*ex2(b0*e1) + c1*ex2(b1*e1) + c2*ex2(b2*e1) + c3*ex2(b3*e1);
            const float v2 = c0*ex2(b0*e2) + c1*ex2(b1*e2) + c2*ex2(b2*e2) + c3*ex2(b3*e2);
            const float v3 = c0*ex2(b0*e3) + c1*ex2(b1*e3) + c2*ex2(b2*e3) + c3*ex2(b3*e3);

            // ---- sequential merge of the 4 sorted edges; flush interior runs ----
            cur = ii.x; acc = v0;
            if (ii.y == cur) acc += v1; else { atomicAdd(out + cur, acc); cur = ii.y; acc = v1; }
            if (ii.z == cur) acc += v2; else { atomicAdd(out + cur, acc); cur = ii.z; acc = v2; }
            if (ii.w == cur) acc += v3; else { atomicAdd(out + cur, acc); cur = ii.w; acc = v3; }
        }

        // ---- warp-segmented inclusive scan over the pending tails ----
        // Edges sorted by idx_i; equal tail ids are contiguous across lanes.
        // Invalid lanes carry cur=-1 and are excluded by the cur>=0 guard.
        #pragma unroll
        for (int o = 1; o < 32; o <<= 1) {
            const float vv = __shfl_up_sync(m, acc, o);
            const int   ss = __shfl_up_sync(m, cur, o);
            if (lane >= o && ss == cur) acc += vv;
        }
        const int nxt = __shfl_down_sync(m, cur, 1);
        if (cur >= 0 && (lane == 31 || nxt != cur)) {
            atomicAdd(out + cur, acc);
        }

        // ---- rotate pipeline ----
        v = vn; valid = nvalid;
        ii = ii_n; jj = jj_n;
    }
}

// ---------------------------------------------------------------------------
// Tail kernel: handles E % 4 leftover edges (0 for this shape, but correct
// in general).
__global__ void zbl_tail_kernel(const float* __restrict__ Dij,
                                const int*   __restrict__ idx_i,
                                const int*   __restrict__ idx_j,
                                const int*   __restrict__ Z,
                                const float* __restrict__ p_ptr,
                                const float* __restrict__ d_ptr,
                                const float* __restrict__ c_ptr,
                                const float* __restrict__ a_ptr,
                                float*       __restrict__ out,
                                int start, int E)
{
    const float p    = __ldg(p_ptr);
    const float invd = 1.0f / __ldg(d_ptr);
    const float NL2E = -1.4426950408889634f * invd;
    const int e = start + blockIdx.x * blockDim.x + threadIdx.x;
    if (e < E) {
        const int   si = __ldg(idx_i + e);
        const int   sj = __ldg(idx_j + e);
        const float zpi = ex2(p * lg2((float)__ldg(Z + si)));
        const float zpj = ex2(p * lg2((float)__ldg(Z + sj)));
        const float ev  = __ldg(Dij + e) * (zpi + zpj);
        float vsum = 0.0f;
        #pragma unroll
        for (int k = 0; k < 4; k++)
            vsum += __ldg(c_ptr + k) * ex2(__ldg(a_ptr + k) * NL2E * ev);
        atomicAdd(out + si, vsum);
    }
}

// ---------------------------------------------------------------------------
extern "C" void kernel_launch(void* const* d_in, const int* in_sizes, int n_in,
                              void* d_out, int out_size)
{
    const int*   Z     = (const int*)  d_in[0];
    const float* Dij   = (const float*)d_in[1];
    const int*   idx_i = (const int*)  d_in[2];
    const int*   idx_j = (const int*)  d_in[3];
    const float* p_ptr = (const float*)d_in[4];
    const float* d_ptr = (const float*)d_in[5];
    const float* c_ptr = (const float*)d_in[6];
    const float* a_ptr = (const float*)d_in[7];
    float* out = (float*)d_out;

    const int E = in_sizes[1];
    const int V = E / 4;            // full 4-edge vectors
    const int tail_start = V * 4;

    // 1) zero the poisoned output (graph-capturable memset node)
    cudaMemsetAsync(out, 0, (size_t)out_size * sizeof(float));

    // 2) pipelined main kernel: each thread handles ITERS vectors grid-stride
    {
        const long long threads_needed = ((long long)V + ITERS - 1) / ITERS;
        const int blocks = (int)((threads_needed + TPB - 1) / TPB);
        zbl_main_kernel<<<blocks, TPB>>>(
            reinterpret_cast<const float4*>(Dij),
            reinterpret_cast<const int4*>(idx_i),
            reinterpret_cast<const int4*>(idx_j),
            Z, p_ptr, d_ptr, c_ptr, a_ptr, out, V);
    }

    // 3) leftover edges (E % 4), if any
    if (tail_start < E) {
        const int n = E - tail_start;
        zbl_tail_kernel<<<(n + 63) / 64, 64>>>(Dij, idx_i, idx_j, Z,
                                               p_ptr, d_ptr, c_ptr, a_ptr,
                                               out, tail_start, E);
    }
}

// round 13
// speedup vs baseline: 1.2653x; 1.2653x over previous
#include <cuda_runtime.h>
#include <cuda_bf16.h>

// ZBL screened nuclear repulsion:
//   expv = Dij/d * (Zi^p + Zj^p)
//   vij  = sum_k c[k] * exp(-a[k]*expv)
//   out  = segment_sum(vij, idx_i)   (idx_i sorted)
//
// R13: R10 skeleton reverted exactly (R12's forced 32-reg/7-CTA build
// collapsed per-thread MLP: occ 88% but 86us — 40 regs is the proven
// sweet spot). One knob: TPB 256 -> 128. Halves each CTA's instantaneous
// LDG burst into the l1tex queue and gives finer work granules for
// late-wave balance; per-thread shape and register budget unchanged.

#define EPT   4
#define TPB   128
#define ITERS 4

__device__ __forceinline__ float ex2(float x) {
    float y;
    asm("ex2.approx.f32 %0, %1;" : "=f"(y) : "f"(x));
    return y;
}
__device__ __forceinline__ float lg2(float x) {
    float y;
    asm("lg2.approx.f32 %0, %1;" : "=f"(y) : "f"(x));
    return y;
}

// ---------------------------------------------------------------------------
__global__ __launch_bounds__(TPB)
void zbl_main_kernel(const float4* __restrict__ Dij4,
                     const int4*   __restrict__ idx_i4,
                     const int4*   __restrict__ idx_j4,
                     const int*    __restrict__ Z,
                     const float*  __restrict__ p_ptr,
                     const float*  __restrict__ d_ptr,
                     const float*  __restrict__ c_ptr,
                     const float*  __restrict__ a_ptr,
                     float*        __restrict__ out,
                     int V)   // number of 4-edge vectors
{
    const float p    = __ldg(p_ptr);
    const float invd = 1.0f / __ldg(d_ptr);
    const float c0 = __ldg(c_ptr + 0), c1 = __ldg(c_ptr + 1);
    const float c2 = __ldg(c_ptr + 2), c3 = __ldg(c_ptr + 3);
    // b_k = -a_k * log2(e) / d : folds exp->ex2 base change and 1/d
    const float NL2E = -1.4426950408889634f * invd;
    const float b0 = __ldg(a_ptr + 0) * NL2E, b1 = __ldg(a_ptr + 1) * NL2E;
    const float b2 = __ldg(a_ptr + 2) * NL2E, b3 = __ldg(a_ptr + 3) * NL2E;

    const int stride = gridDim.x * blockDim.x;
    int v = blockIdx.x * blockDim.x + threadIdx.x;

    const unsigned m = 0xFFFFFFFFu;
    const int lane = threadIdx.x & 31;

    // ---- prologue: prefetch iteration 0's index vectors (gather roots) ----
    bool valid = (v < V);
    int4 ii = make_int4(0, 0, 0, 0);
    int4 jj = make_int4(0, 0, 0, 0);
    if (valid) {
        ii = __ldcs(idx_i4 + v);
        jj = __ldcs(idx_j4 + v);
    }

    #pragma unroll 1
    for (int k = 0; k < ITERS; k++) {
        int   cur = -1;     // pending segment id (tail)
        float acc = 0.0f;   // pending segment sum

        // next iteration's index prefetch (issued before this iteration's
        // dependent work so the DRAM hop overlaps the gather+math+scan)
        const int  vn     = v + stride;
        const bool nvalid = (k + 1 < ITERS) && (vn < V);
        int4 ii_n = make_int4(0, 0, 0, 0);
        int4 jj_n = make_int4(0, 0, 0, 0);
        if (nvalid) {
            ii_n = __ldcs(idx_i4 + vn);
            jj_n = __ldcs(idx_j4 + vn);
        }

        if (valid) {
            // ---- Dij load: independent of the gather chain, self-hiding ----
            const float4 dd = __ldcs(Dij4 + v);

            // ---- 8 independent scalar gathers from the input Z array ----
            const int zi0 = __ldg(Z + ii.x), zi1 = __ldg(Z + ii.y);
            const int zi2 = __ldg(Z + ii.z), zi3 = __ldg(Z + ii.w);
            const int zj0 = __ldg(Z + jj.x), zj1 = __ldg(Z + jj.y);
            const int zj2 = __ldg(Z + jj.z), zj3 = __ldg(Z + jj.w);

            // ---- z^p via MUFU: ex2(p*lg2 z); z=0 -> -inf -> 0 = pow(0,p) ----
            const float fi0 = ex2(p * lg2((float)zi0));
            const float fi1 = ex2(p * lg2((float)zi1));
            const float fi2 = ex2(p * lg2((float)zi2));
            const float fi3 = ex2(p * lg2((float)zi3));
            const float fj0 = ex2(p * lg2((float)zj0));
            const float fj1 = ex2(p * lg2((float)zj1));
            const float fj2 = ex2(p * lg2((float)zj2));
            const float fj3 = ex2(p * lg2((float)zj3));

            const float e0 = dd.x * (fi0 + fj0);
            const float e1 = dd.y * (fi1 + fj1);
            const float e2 = dd.z * (fi2 + fj2);
            const float e3 = dd.w * (fi3 + fj3);

            const float v0 = c0*ex2(b0*e0) + c1*ex2(b1*e0) + c2*ex2(b2*e0) + c3*ex2(b3*e0);
            const float v1 = c0*ex2(b0*e1) + c1*ex2(b1*e1) + c2*ex2(b2*e1) + c3*ex2(b3*e1);
            const float v2 = c0*ex2(b0*e2) + c1*ex2(b1*e2) + c2*ex2(b2*e2) + c3*ex2(b3*e2);
            const float v3 = c0*ex2(b0*e3) + c1*ex2(b1*e3) + c2*ex2(b2*e3) + c3*ex2(b3*e3);

            // ---- sequential merge of the 4 sorted edges; flush interior runs ----
            cur = ii.x; acc = v0;
            if (ii.y == cur) acc += v1; else { atomicAdd(out + cur, acc); cur = ii.y; acc = v1; }
            if (ii.z == cur) acc += v2; else { atomicAdd(out + cur, acc); cur = ii.z; acc = v2; }
            if (ii.w == cur) acc += v3; else { atomicAdd(out + cur, acc); cur = ii.w; acc = v3; }
        }

        // ---- warp-segmented inclusive scan over the pending tails ----
        // Edges sorted by idx_i; equal tail ids are contiguous across lanes.
        // Invalid lanes carry cur=-1 and are excluded by the cur>=0 guard.
        #pragma unroll
        for (int o = 1; o < 32; o <<= 1) {
            const float vv = __shfl_up_sync(m, acc, o);
            const int   ss = __shfl_up_sync(m, cur, o);
            if (lane >= o && ss == cur) acc += vv;
        }
        const int nxt = __shfl_down_sync(m, cur, 1);
        if (cur >= 0 && (lane == 31 || nxt != cur)) {
            atomicAdd(out + cur, acc);
        }

        // ---- rotate pipeline ----
        v = vn; valid = nvalid;
        ii = ii_n; jj = jj_n;
    }
}

// ---------------------------------------------------------------------------
// Tail kernel: handles E % 4 leftover edges (0 for this shape, but correct
// in general).
__global__ void zbl_tail_kernel(const float* __restrict__ Dij,
                                const int*   __restrict__ idx_i,
                                const int*   __restrict__ idx_j,
                                const int*   __restrict__ Z,
                                const float* __restrict__ p_ptr,
                                const float* __restrict__ d_ptr,
                                const float* __restrict__ c_ptr,
                                const float* __restrict__ a_ptr,
                                float*       __restrict__ out,
                                int start, int E)
{
    const float p    = __ldg(p_ptr);
    const float invd = 1.0f / __ldg(d_ptr);
    const float NL2E = -1.4426950408889634f * invd;
    const int e = start + blockIdx.x * blockDim.x + threadIdx.x;
    if (e < E) {
        const int   si = __ldg(idx_i + e);
        const int   sj = __ldg(idx_j + e);
        const float zpi = ex2(p * lg2((float)__ldg(Z + si)));
        const float zpj = ex2(p * lg2((float)__ldg(Z + sj)));
        const float ev  = __ldg(Dij + e) * (zpi + zpj);
        float vsum = 0.0f;
        #pragma unroll
        for (int k = 0; k < 4; k++)
            vsum += __ldg(c_ptr + k) * ex2(__ldg(a_ptr + k) * NL2E * ev);
        atomicAdd(out + si, vsum);
    }
}

// ---------------------------------------------------------------------------
extern "C" void kernel_launch(void* const* d_in, const int* in_sizes, int n_in,
                              void* d_out, int out_size)
{
    const int*   Z     = (const int*)  d_in[0];
    const float* Dij   = (const float*)d_in[1];
    const int*   idx_i = (const int*)  d_in[2];
    const int*   idx_j = (const int*)  d_in[3];
    const float* p_ptr = (const float*)d_in[4];
    const float* d_ptr = (const float*)d_in[5];
    const float* c_ptr = (const float*)d_in[6];
    const float* a_ptr = (const float*)d_in[7];
    float* out = (float*)d_out;

    const int E = in_sizes[1];
    const int V = E / 4;            // full 4-edge vectors
    const int tail_start = V * 4;

    // 1) zero the poisoned output (graph-capturable memset node)
    cudaMemsetAsync(out, 0, (size_t)out_size * sizeof(float));

    // 2) pipelined main kernel: each thread handles ITERS vectors grid-stride
    {
        const long long threads_needed = ((long long)V + ITERS - 1) / ITERS;
        const int blocks = (int)((threads_needed + TPB - 1) / TPB);
        zbl_main_kernel<<<blocks, TPB>>>(
            reinterpret_cast<const float4*>(Dij),
            reinterpret_cast<const int4*>(idx_i),
            reinterpret_cast<const int4*>(idx_j),
            Z, p_ptr, d_ptr, c_ptr, a_ptr, out, V);
    }

    // 3) leftover edges (E % 4), if any
    if (tail_start < E) {
        const int n = E - tail_start;
        zbl_tail_kernel<<<(n + 63) / 64, 64>>>(Dij, idx_i, idx_j, Z,
                                               p_ptr, d_ptr, c_ptr, a_ptr,
                                               out, tail_start, E);
    }
}

// round 14
// speedup vs baseline: 1.2707x; 1.0042x over previous
#include <cuda_runtime.h>
#include <cuda_bf16.h>

// ZBL screened nuclear repulsion — FINAL (champion config, = R10):
//   expv = Dij/d * (Zi^p + Zj^p)
//   vij  = sum_k c[k] * exp(-a[k]*expv)
//   out  = segment_sum(vij, idx_i)   (idx_i sorted)
//
// Architecture (settled over 12 measured rounds):
//  - EPT=4 edges/thread via float4/int4 streaming loads (.cs evict-first);
//    deeper front-batching overflows the 248-entry l1tex wavefront queue.
//  - ITERS=4 fixed-trip loop with next-iteration idx prefetch (hides the
//    DRAM hop of the stream loads behind the gather+math+scan of the
//    current iteration); Dij loaded in-body (self-hiding).
//  - z^p computed on MUFU (ex2(p*lg2 z)) — keeps the zp lookup off the
//    binding l1tex pipe; 1/d folded into the exp coefficients.
//  - Z gathered directly from the INPUT array (module-global scratch
//    tables regress ~1.5x — small-page PTW traffic on the l1tex pipe).
//  - Sorted segment-sum: per-thread run merge + warp-segmented shuffle
//    scan; one atomicAdd per warp-run boundary (~4.6M REDs total).
//  - 40 regs / 256 TPB: the only viable point on the occupancy/MLP curve
//    (32 regs collapses load batching; reg granularity forbids 36).
// Status: l1tex wavefront floor reached (L1-busy ~53us ~= j-gather floor).

#define EPT   4
#define TPB   256
#define ITERS 4

__device__ __forceinline__ float ex2(float x) {
    float y;
    asm("ex2.approx.f32 %0, %1;" : "=f"(y) : "f"(x));
    return y;
}
__device__ __forceinline__ float lg2(float x) {
    float y;
    asm("lg2.approx.f32 %0, %1;" : "=f"(y) : "f"(x));
    return y;
}

// ---------------------------------------------------------------------------
__global__ __launch_bounds__(TPB)
void zbl_main_kernel(const float4* __restrict__ Dij4,
                     const int4*   __restrict__ idx_i4,
                     const int4*   __restrict__ idx_j4,
                     const int*    __restrict__ Z,
                     const float*  __restrict__ p_ptr,
                     const float*  __restrict__ d_ptr,
                     const float*  __restrict__ c_ptr,
                     const float*  __restrict__ a_ptr,
                     float*        __restrict__ out,
                     int V)   // number of 4-edge vectors
{
    const float p    = __ldg(p_ptr);
    const float invd = 1.0f / __ldg(d_ptr);
    const float c0 = __ldg(c_ptr + 0), c1 = __ldg(c_ptr + 1);
    const float c2 = __ldg(c_ptr + 2), c3 = __ldg(c_ptr + 3);
    // b_k = -a_k * log2(e) / d : folds exp->ex2 base change and 1/d
    const float NL2E = -1.4426950408889634f * invd;
    const float b0 = __ldg(a_ptr + 0) * NL2E, b1 = __ldg(a_ptr + 1) * NL2E;
    const float b2 = __ldg(a_ptr + 2) * NL2E, b3 = __ldg(a_ptr + 3) * NL2E;

    const int stride = gridDim.x * blockDim.x;
    int v = blockIdx.x * blockDim.x + threadIdx.x;

    const unsigned m = 0xFFFFFFFFu;
    const int lane = threadIdx.x & 31;

    // ---- prologue: prefetch iteration 0's index vectors (gather roots) ----
    bool valid = (v < V);
    int4 ii = make_int4(0, 0, 0, 0);
    int4 jj = make_int4(0, 0, 0, 0);
    if (valid) {
        ii = __ldcs(idx_i4 + v);
        jj = __ldcs(idx_j4 + v);
    }

    #pragma unroll 1
    for (int k = 0; k < ITERS; k++) {
        int   cur = -1;     // pending segment id (tail)
        float acc = 0.0f;   // pending segment sum

        // next iteration's index prefetch (issued before this iteration's
        // dependent work so the DRAM hop overlaps the gather+math+scan)
        const int  vn     = v + stride;
        const bool nvalid = (k + 1 < ITERS) && (vn < V);
        int4 ii_n = make_int4(0, 0, 0, 0);
        int4 jj_n = make_int4(0, 0, 0, 0);
        if (nvalid) {
            ii_n = __ldcs(idx_i4 + vn);
            jj_n = __ldcs(idx_j4 + vn);
        }

        if (valid) {
            // ---- Dij load: independent of the gather chain, self-hiding ----
            const float4 dd = __ldcs(Dij4 + v);

            // ---- 8 independent scalar gathers from the input Z array ----
            const int zi0 = __ldg(Z + ii.x), zi1 = __ldg(Z + ii.y);
            const int zi2 = __ldg(Z + ii.z), zi3 = __ldg(Z + ii.w);
            const int zj0 = __ldg(Z + jj.x), zj1 = __ldg(Z + jj.y);
            const int zj2 = __ldg(Z + jj.z), zj3 = __ldg(Z + jj.w);

            // ---- z^p via MUFU: ex2(p*lg2 z); z=0 -> -inf -> 0 = pow(0,p) ----
            const float fi0 = ex2(p * lg2((float)zi0));
            const float fi1 = ex2(p * lg2((float)zi1));
            const float fi2 = ex2(p * lg2((float)zi2));
            const float fi3 = ex2(p * lg2((float)zi3));
            const float fj0 = ex2(p * lg2((float)zj0));
            const float fj1 = ex2(p * lg2((float)zj1));
            const float fj2 = ex2(p * lg2((float)zj2));
            const float fj3 = ex2(p * lg2((float)zj3));

            const float e0 = dd.x * (fi0 + fj0);
            const float e1 = dd.y * (fi1 + fj1);
            const float e2 = dd.z * (fi2 + fj2);
            const float e3 = dd.w * (fi3 + fj3);

            const float v0 = c0*ex2(b0*e0) + c1*ex2(b1*e0) + c2*ex2(b2*e0) + c3*ex2(b3*e0);
            const float v1 = c0*ex2(b0*e1) + c1*ex2(b1*e1) + c2*ex2(b2*e1) + c3*ex2(b3*e1);
            const float v2 = c0*ex2(b0*e2) + c1*ex2(b1*e2) + c2*ex2(b2*e2) + c3*ex2(b3*e2);
            const float v3 = c0*ex2(b0*e3) + c1*ex2(b1*e3) + c2*ex2(b2*e3) + c3*ex2(b3*e3);

            // ---- sequential merge of the 4 sorted edges; flush interior runs ----
            cur = ii.x; acc = v0;
            if (ii.y == cur) acc += v1; else { atomicAdd(out + cur, acc); cur = ii.y; acc = v1; }
            if (ii.z == cur) acc += v2; else { atomicAdd(out + cur, acc); cur = ii.z; acc = v2; }
            if (ii.w == cur) acc += v3; else { atomicAdd(out + cur, acc); cur = ii.w; acc = v3; }
        }

        // ---- warp-segmented inclusive scan over the pending tails ----
        // Edges sorted by idx_i; equal tail ids are contiguous across lanes.
        // Invalid lanes carry cur=-1 and are excluded by the cur>=0 guard.
        #pragma unroll
        for (int o = 1; o < 32; o <<= 1) {
            const float vv = __shfl_up_sync(m, acc, o);
            const int   ss = __shfl_up_sync(m, cur, o);
            if (lane >= o && ss == cur) acc += vv;
        }
        const int nxt = __shfl_down_sync(m, cur, 1);
        if (cur >= 0 && (lane == 31 || nxt != cur)) {
            atomicAdd(out + cur, acc);
        }

        // ---- rotate pipeline ----
        v = vn; valid = nvalid;
        ii = ii_n; jj = jj_n;
    }
}

// ---------------------------------------------------------------------------
// Tail kernel: handles E % 4 leftover edges (0 for this shape, but correct
// in general).
__global__ void zbl_tail_kernel(const float* __restrict__ Dij,
                                const int*   __restrict__ idx_i,
                                const int*   __restrict__ idx_j,
                                const int*   __restrict__ Z,
                                const float* __restrict__ p_ptr,
                                const float* __restrict__ d_ptr,
                                const float* __restrict__ c_ptr,
                                const float* __restrict__ a_ptr,
                                float*       __restrict__ out,
                                int start, int E)
{
    const float p    = __ldg(p_ptr);
    const float invd = 1.0f / __ldg(d_ptr);
    const float NL2E = -1.4426950408889634f * invd;
    const int e = start + blockIdx.x * blockDim.x + threadIdx.x;
    if (e < E) {
        const int   si = __ldg(idx_i + e);
        const int   sj = __ldg(idx_j + e);
        const float zpi = ex2(p * lg2((float)__ldg(Z + si)));
        const float zpj = ex2(p * lg2((float)__ldg(Z + sj)));
        const float ev  = __ldg(Dij + e) * (zpi + zpj);
        float vsum = 0.0f;
        #pragma unroll
        for (int k = 0; k < 4; k++)
            vsum += __ldg(c_ptr + k) * ex2(__ldg(a_ptr + k) * NL2E * ev);
        atomicAdd(out + si, vsum);
    }
}

// ---------------------------------------------------------------------------
extern "C" void kernel_launch(void* const* d_in, const int* in_sizes, int n_in,
                              void* d_out, int out_size)
{
    const int*   Z     = (const int*)  d_in[0];
    const float* Dij   = (const float*)d_in[1];
    const int*   idx_i = (const int*)  d_in[2];
    const int*   idx_j = (const int*)  d_in[3];
    const float* p_ptr = (const float*)d_in[4];
    const float* d_ptr = (const float*)d_in[5];
    const float* c_ptr = (const float*)d_in[6];
    const float* a_ptr = (const float*)d_in[7];
    float* out = (float*)d_out;

    const int E = in_sizes[1];
    const int V = E / 4;            // full 4-edge vectors
    const int tail_start = V * 4;

    // 1) zero the poisoned output (graph-capturable memset node; must
    //    precede the atomics, so it cannot be overlapped with the kernel)
    cudaMemsetAsync(out, 0, (size_t)out_size * sizeof(float));

    // 2) pipelined main kernel: each thread handles ITERS vectors grid-stride
    {
        const long long threads_needed = ((long long)V + ITERS - 1) / ITERS;
        const int blocks = (int)((threads_needed + TPB - 1) / TPB);
        zbl_main_kernel<<<blocks, TPB>>>(
            reinterpret_cast<const float4*>(Dij),
            reinterpret_cast<const int4*>(idx_i),
            reinterpret_cast<const int4*>(idx_j),
            Z, p_ptr, d_ptr, c_ptr, a_ptr, out, V);
    }

    // 3) leftover edges (E % 4), if any
    if (tail_start < E) {
        const int n = E - tail_start;
        zbl_tail_kernel<<<(n + 63) / 64, 64>>>(Dij, idx_i, idx_j, Z,
                                               p_ptr, d_ptr, c_ptr, a_ptr,
                                               out, tail_start, E);
    }
}